// round 5
// baseline (speedup 1.0000x reference)
#include <cuda_runtime.h>
#include <cuda_fp16.h>
#include <math.h>
#include <stdint.h>

#define HIDDEN 256
#define T_HOR  24
#define FMET   16
#define B_SZ   16
#define N_SZ   1000
#define GRP    5
#define TPB    256
#define NCTA   (B_SZ * (N_SZ / GRP))   // 3200
#define EPS_LN 1e-5f

// ---- smem layout (bytes) ----
#define OFF_AHI   0         // A hi fragments, 64KB
#define OFF_ALO   65536     // A lo fragments, 64KB
#define OFF_B     131072    // B double buffer, 2 x 32KB
// phase-A staging window overlaps B buffers (dead before first cp.async)
#define OFF_QB    131072    // 24*258*4 = 24768
#define OFF_WFM   155840    // 16384
#define OFF_FH    172224    // 5120
#define OFF_FM    177344    // 7680
#define OFF_GAM   185024    // 1024
// persistent smalls
#define OFF_STS   196608    // 1024
#define OFF_STS2  197632    // 1024
#define OFF_RED   198656    // 4096 (128 rows x 8 slots)
#define OFF_CS    202752    // 1024
#define OFF_GS    203776    // 1024
#define OFF_W2S   204800    // 1024
#define SMEM_TOTAL 205824

// W1 pre-packed fp16 hi/lo in nt-pair mma-fragment layout (u32 words):
// [chunk 8]{8192} [split 2]{4096} [kstep 2]{2048} [ntpair 16]{128} [lane 32]{4} [slot 4]
//   slot = (nt&1)*2 + reg   (reg = k8-half)
__device__ __align__(16) uint32_t g_Bpk[8 * 8192];
__device__ float g_C[HIDDEN];
__device__ float g_G[HIDDEN];
__device__ float g_W2[HIDDEN];

__global__ void prep_w1(const float* __restrict__ W1) {
    const int k0 = blockIdx.x * 2;
    const int n  = threadIdx.x;
    float v0 = W1[k0 * 256 + n];
    float v1 = W1[(k0 + 1) * 256 + n];
    __half h0 = __float2half_rn(v0);
    __half h1 = __float2half_rn(v1);
    __half l0 = __float2half_rn(v0 - __half2float(h0));
    __half l1 = __float2half_rn(v1 - __half2float(h1));
    const int chunk = k0 >> 5;
    const int kstep = (k0 >> 4) & 1;
    const int kk    = k0 & 15;
    const int ntile = n >> 3;
    const int lane  = ((n & 7) << 2) | ((kk & 7) >> 1);
    const int reg   = (kk >> 3) & 1;
    const int pair  = ntile >> 1;
    const int slot  = (ntile & 1) * 2 + reg;
    const int base  = chunk * 8192 + kstep * 2048 + pair * 128 + lane * 4 + slot;
    __half2 hp = __halves2half2(h0, h1);
    __half2 lp = __halves2half2(l0, l1);
    g_Bpk[base]        = *(uint32_t*)&hp;     // split 0 (hi)
    g_Bpk[base + 4096] = *(uint32_t*)&lp;     // split 1 (lo)
}

__global__ void prep_cg(const float* __restrict__ W1, const float* __restrict__ gamma,
                        const float* __restrict__ beta, const float* __restrict__ b1,
                        const float* __restrict__ W2) {
    int j = threadIdx.x;
    float P = 0.f, G = 0.f;
    for (int c = 0; c < 256; c++) {
        float w = W1[c * 256 + j];
        P = fmaf(beta[c], w, P);
        G = fmaf(gamma[c], w, G);
    }
    g_C[j]  = P + b1[j];
    g_G[j]  = G;
    g_W2[j] = W2[j];
}

__device__ __forceinline__ uint32_t smem_u32(const void* p) {
    uint32_t a;
    asm("{ .reg .u64 t; cvta.to.shared.u64 t, %1; cvt.u32.u64 %0, t; }" : "=r"(a) : "l"(p));
    return a;
}
__device__ __forceinline__ uint64_t to_global(const void* p) {
    uint64_t a; asm("cvta.to.global.u64 %0, %1;" : "=l"(a) : "l"(p)); return a;
}
__device__ __forceinline__ void cp_async16(uint32_t s, uint64_t g) {
    asm volatile("cp.async.cg.shared.global [%0], [%1], 16;" :: "r"(s), "l"(g) : "memory");
}
#define CP_COMMIT() asm volatile("cp.async.commit_group;" ::: "memory")
#define CP_WAIT1()  asm volatile("cp.async.wait_group 1;" ::: "memory")
#define CP_WAIT0()  asm volatile("cp.async.wait_group 0;" ::: "memory")

#define LDS128(r, addr) \
    asm volatile("ld.shared.v4.b32 {%0,%1,%2,%3}, [%4];" \
        : "=r"((r)[0]), "=r"((r)[1]), "=r"((r)[2]), "=r"((r)[3]) : "r"(addr))

// fp16 inputs, fp32 accumulate
#define MMA_F32(d, a, b0, b1v) \
    asm volatile("mma.sync.aligned.m16n8k16.row.col.f32.f16.f16.f32 " \
        "{%0,%1,%2,%3}, {%4,%5,%6,%7}, {%8,%9}, {%0,%1,%2,%3};" \
        : "+f"((d)[0]), "+f"((d)[1]), "+f"((d)[2]), "+f"((d)[3]) \
        : "r"((a)[0]), "r"((a)[1]), "r"((a)[2]), "r"((a)[3]), \
          "r"(b0), "r"(b1v))

// fp16 inputs, fp16 accumulate (cross terms; 2x rate if HW supports)
#define MMA_F16(d, a, b0, b1v) \
    asm volatile("mma.sync.aligned.m16n8k16.row.col.f16.f16.f16.f16 " \
        "{%0,%1}, {%2,%3,%4,%5}, {%6,%7}, {%0,%1};" \
        : "+r"((d)[0]), "+r"((d)[1]) \
        : "r"((a)[0]), "r"((a)[1]), "r"((a)[2]), "r"((a)[3]), \
          "r"(b0), "r"(b1v))

__device__ __forceinline__ float gelu_exact(float x) {
    return 0.5f * x * (1.0f + erff(x * 0.70710678118654752440f));
}

__global__ void __launch_bounds__(TPB)
dhh_main(const float* __restrict__ final_h,
         const float* __restrict__ future_met,
         const float* __restrict__ step_q,
         const float* __restrict__ W_fm,
         const float* __restrict__ b_fm,
         const float* __restrict__ gamma,
         const float* __restrict__ b2,
         float* __restrict__ out)
{
    extern __shared__ __align__(1024) char smem[];
    float* smf = (float*)smem;
    const uint32_t sbase = smem_u32(smem);
    const int tid  = threadIdx.x;
    const int w    = tid >> 5;
    const int lane = tid & 31;

    const int b  = blockIdx.x / (N_SZ / GRP);
    const int n0 = (blockIdx.x % (N_SZ / GRP)) * GRP;

    // ---- stage phase-A inputs + persistent constants ----
    for (int i = tid; i < T_HOR * 256; i += TPB) {
        int t = i >> 8, c = i & 255;
        smf[OFF_QB / 4 + t * 258 + c] = step_q[i] + b_fm[c];
    }
    for (int i = tid; i < FMET * 256; i += TPB)
        smf[OFF_WFM / 4 + i] = W_fm[i];
    for (int i = tid; i < GRP * 256; i += TPB)
        smf[OFF_FH / 4 + i] = final_h[((size_t)b * N_SZ + n0) * 256 + i];
    for (int i = tid; i < GRP * T_HOR * FMET; i += TPB) {
        int ln = i / (T_HOR * FMET), r = i % (T_HOR * FMET);
        int t = r >> 4, f = r & 15;
        smf[OFF_FM / 4 + (ln * T_HOR + t) * FMET + f] =
            future_met[((size_t)(b * T_HOR + t) * N_SZ + (n0 + ln)) * FMET + f];
    }
    if (tid < 256) {
        smf[OFF_GAM / 4 + tid] = gamma[tid];
        smf[OFF_CS  / 4 + tid] = g_C[tid];
        smf[OFF_GS  / 4 + tid] = g_G[tid];
        smf[OFF_W2S / 4 + tid] = g_W2[tid];
    }
    __syncthreads();

    // ---- phase A: combined -> gamma-scaled fp16 hi/lo in fragment layout ----
    {
        const int m = tid & 127, half = tid >> 7;
        int ln = m / 24; if (ln > 4) ln = 4;
        const int t = m % 24;
        float fmv[FMET];
#pragma unroll
        for (int f = 0; f < FMET; f++)
            fmv[f] = smf[OFF_FM / 4 + (ln * T_HOR + t) * FMET + f];

        float s = 0.f, s2 = 0.f;
        const int cb = half * 128;
        const uint32_t mbase = (uint32_t)(m >> 4) * 16;
        const uint32_t lane_m = (uint32_t)(m & 7) << 2;
        const uint32_t reg_m  = ((m & 15) >= 8) ? 1u : 0u;
#pragma unroll 4
        for (int i = 0; i < 64; i++) {
            const int c = cb + 2 * i;
            float2 qb = *(const float2*)&smf[OFF_QB / 4 + t * 258 + c];
            float2 fh = *(const float2*)&smf[OFF_FH / 4 + ln * 256 + c];
            float v0 = qb.x + fh.x, v1 = qb.y + fh.y;
#pragma unroll
            for (int f = 0; f < FMET; f++) {
                float2 wf = *(const float2*)&smf[OFF_WFM / 4 + f * 256 + c];
                v0 = fmaf(fmv[f], wf.x, v0);
                v1 = fmaf(fmv[f], wf.y, v1);
            }
            s += v0 + v1;
            s2 = fmaf(v0, v0, s2);
            s2 = fmaf(v1, v1, s2);
            float2 g2 = *(const float2*)&smf[OFF_GAM / 4 + c];
            float a0 = v0 * g2.x, a1 = v1 * g2.y;
            __half h0 = __float2half_rn(a0);
            __half h1 = __float2half_rn(a1);
            __half l0 = __float2half_rn(a0 - __half2float(h0));
            __half l1 = __float2half_rn(a1 - __half2float(h1));
            __half2 hp = __halves2half2(h0, h1);
            __half2 lp = __halves2half2(l0, l1);

            const uint32_t kk   = (uint32_t)(c & 15);
            const uint32_t lnA  = lane_m | ((kk & 7) >> 1);
            const uint32_t reg  = ((kk & 8) ? 2u : 0u) | reg_m;
            uint32_t off = ((mbase + (uint32_t)(c >> 4)) << 9) + (lnA << 4) + (reg << 2);
            off ^= (off >> 2) & 0x60;
            *(uint32_t*)(smem + OFF_AHI + off) = *(uint32_t*)&hp;
            *(uint32_t*)(smem + OFF_ALO + off) = *(uint32_t*)&lp;
        }
        smf[OFF_STS  / 4 + m * 2 + half] = s;
        smf[OFF_STS2 / 4 + m * 2 + half] = s2;
    }
    __syncthreads();

    // ---- GEMM: 8 k32-chunks; hi*hi in f32 acc, crosses in f16 acc ----
    const int wm = w & 3, wn = w >> 2;
    float acc0[16][4], acc1[16][4];
    uint32_t cr0[16][2], cr1[16][2];
#pragma unroll
    for (int nt = 0; nt < 16; nt++) {
#pragma unroll
        for (int e = 0; e < 4; e++) { acc0[nt][e] = 0.f; acc1[nt][e] = 0.f; }
        cr0[nt][0] = 0u; cr0[nt][1] = 0u;
        cr1[nt][0] = 0u; cr1[nt][1] = 0u;
    }

    const uint32_t laneOff = ((uint32_t)lane << 4) ^ (((uint32_t)lane & 0x18) << 2);
    const uint64_t gB = to_global(g_Bpk);

    // prefetch chunk 0
    {
        uint32_t d = sbase + OFF_B + tid * 16;
        uint64_t s = gB + tid * 16;
#pragma unroll
        for (int i = 0; i < 8; i++) cp_async16(d + i * 4096, s + i * 4096);
        CP_COMMIT();
    }

    for (int c = 0; c < 8; c++) {
        if (c < 7) {
            uint32_t d = sbase + OFF_B + ((c + 1) & 1) * 32768 + tid * 16;
            uint64_t s = gB + (size_t)(c + 1) * 32768 + tid * 16;
#pragma unroll
            for (int i = 0; i < 8; i++) cp_async16(d + i * 4096, s + i * 4096);
            CP_COMMIT();
            CP_WAIT1();
        } else {
            CP_WAIT0();
        }
        __syncthreads();

        const uint32_t bufB = sbase + OFF_B + (uint32_t)(c & 1) * 32768;
#pragma unroll
        for (int kl = 0; kl < 2; kl++) {
            const uint32_t ks = (uint32_t)(c * 2 + kl);
            uint32_t ah0[4], ah1[4], al0[4], al1[4];
            const uint32_t aRow0 = (((uint32_t)(wm * 2 + 0) * 16 + ks) << 9) + laneOff;
            const uint32_t aRow1 = (((uint32_t)(wm * 2 + 1) * 16 + ks) << 9) + laneOff;
            LDS128(ah0, sbase + OFF_AHI + aRow0);
            LDS128(ah1, sbase + OFF_AHI + aRow1);
            LDS128(al0, sbase + OFF_ALO + aRow0);
            LDS128(al1, sbase + OFF_ALO + aRow1);

            // hi: split0, lo: split1 (+16384 bytes)
            const uint32_t bHi = bufB + (uint32_t)kl * 8192 +
                                 (uint32_t)(wn * 8) * 512 + (uint32_t)lane * 16;
            const uint32_t bLo = bHi + 16384;
#pragma unroll
            for (int p = 0; p < 8; p++) {
                uint32_t bh[4], bl[4];
                LDS128(bh, bHi + p * 512);
                LDS128(bl, bLo + p * 512);
                const int nte = 2 * p, nto = 2 * p + 1;
                // hi*hi -> f32 acc
                MMA_F32(acc0[nte], ah0, bh[0], bh[1]);
                MMA_F32(acc1[nte], ah1, bh[0], bh[1]);
                MMA_F32(acc0[nto], ah0, bh[2], bh[3]);
                MMA_F32(acc1[nto], ah1, bh[2], bh[3]);
                // crosses -> f16 acc
                MMA_F16(cr0[nte], ah0, bl[0], bl[1]);
                MMA_F16(cr0[nte], al0, bh[0], bh[1]);
                MMA_F16(cr1[nte], ah1, bl[0], bl[1]);
                MMA_F16(cr1[nte], al1, bh[0], bh[1]);
                MMA_F16(cr0[nto], ah0, bl[2], bl[3]);
                MMA_F16(cr0[nto], al0, bh[2], bh[3]);
                MMA_F16(cr1[nto], ah1, bl[2], bl[3]);
                MMA_F16(cr1[nto], al1, bh[2], bh[3]);
            }
        }
        __syncthreads();
    }

    // ---- epilogue: LN fold + exact GELU + W2 dot ----
    {
        const int g = lane >> 2;
        float rstd[4], mr[4];
#pragma unroll
        for (int q = 0; q < 4; q++) {
            const int row = wm * 32 + q * 8 + g;
            const float ssum = smf[OFF_STS / 4 + row * 2] + smf[OFF_STS / 4 + row * 2 + 1];
            const float q2   = smf[OFF_STS2 / 4 + row * 2] + smf[OFF_STS2 / 4 + row * 2 + 1];
            const float mu   = ssum * (1.0f / HIDDEN);
            const float var  = q2 * (1.0f / HIDDEN) - mu * mu;
            rstd[q] = rsqrtf(var + EPS_LN);
            mr[q]   = mu * rstd[q];
        }
        float part[4] = {0.f, 0.f, 0.f, 0.f};
#pragma unroll
        for (int nt = 0; nt < 16; nt++) {
            float2 cx[4];
            cx[0] = __half22float2(*(__half2*)&cr0[nt][0]);
            cx[1] = __half22float2(*(__half2*)&cr0[nt][1]);
            cx[2] = __half22float2(*(__half2*)&cr1[nt][0]);
            cx[3] = __half22float2(*(__half2*)&cr1[nt][1]);
#pragma unroll
            for (int e = 0; e < 2; e++) {
                const int j = (wn * 16 + nt) * 8 + (lane & 3) * 2 + e;
                const float csj = smf[OFF_CS / 4 + j];
                const float gsj = smf[OFF_GS / 4 + j];
                const float w2j = smf[OFF_W2S / 4 + j];
#pragma unroll
                for (int q = 0; q < 4; q++) {
                    const float base = (q < 2) ? acc0[nt][(q & 1) * 2 + e]
                                               : acc1[nt][(q & 1) * 2 + e];
                    const float2 cpair = cx[(q < 2 ? 0 : 2) + (q & 1)];
                    const float S = base + (e ? cpair.y : cpair.x);
                    const float o = fmaf(rstd[q], S, csj) - mr[q] * gsj;
                    part[q] = fmaf(gelu_exact(o), w2j, part[q]);
                }
            }
        }
        const int slot = ((lane & 3) << 1) | wn;
#pragma unroll
        for (int q = 0; q < 4; q++) {
            const int row = wm * 32 + q * 8 + g;
            smf[OFF_RED / 4 + row * 8 + slot] = part[q];
        }
    }
    __syncthreads();

    if (tid < GRP * T_HOR) {
        const int ln = tid / T_HOR, t = tid % T_HOR;
        const float* rr = &smf[OFF_RED / 4 + tid * 8];
        float s = rr[0] + rr[1] + rr[2] + rr[3] + rr[4] + rr[5] + rr[6] + rr[7];
        out[(size_t)(b * T_HOR + t) * N_SZ + (n0 + ln)] = s + b2[0];
    }
}

extern "C" void kernel_launch(void* const* d_in, const int* in_sizes, int n_in,
                              void* d_out, int out_size) {
    const float* final_h    = (const float*)d_in[0];
    const float* future_met = (const float*)d_in[1];
    const float* step_q     = (const float*)d_in[2];
    const float* W_fm       = (const float*)d_in[3];
    const float* b_fm       = (const float*)d_in[4];
    const float* gamma      = (const float*)d_in[5];
    const float* beta       = (const float*)d_in[6];
    const float* W1         = (const float*)d_in[7];
    const float* b1         = (const float*)d_in[8];
    const float* W2         = (const float*)d_in[9];
    const float* b2         = (const float*)d_in[10];
    float* out = (float*)d_out;

    prep_w1<<<128, 256>>>(W1);
    prep_cg<<<1, 256>>>(W1, gamma, beta, b1, W2);

    cudaFuncSetAttribute(dhh_main, cudaFuncAttributeMaxDynamicSharedMemorySize, SMEM_TOTAL);
    dhh_main<<<NCTA, TPB, SMEM_TOTAL>>>(final_h, future_met, step_q, W_fm, b_fm,
                                        gamma, b2, out);
}

// round 6
// speedup vs baseline: 1.2321x; 1.2321x over previous
#include <cuda_runtime.h>
#include <cuda_fp16.h>
#include <math.h>
#include <stdint.h>

#define HIDDEN 256
#define T_HOR  24
#define FMET   16
#define B_SZ   16
#define N_SZ   1000
#define GRP    5
#define TPB    256
#define NCTA   (B_SZ * (N_SZ / GRP))   // 3200
#define EPS_LN 1e-5f

// ---- smem layout (bytes) ----
#define OFF_AHI   0         // A hi fragments, 64KB
#define OFF_B     65536     // B double buffer, 2 x 32KB
// phase-A staging window overlaps B buffers (dead before first cp.async)
#define OFF_QB    65536     // 24*258*4 = 24768
#define OFF_WFM   90304     // 16384
#define OFF_FH    106688    // 5120
#define OFF_FM    111808    // 7680
#define OFF_GAM   119488    // 1024
// persistent smalls
#define OFF_STS   131072    // 1024
#define OFF_STS2  132096    // 1024
#define OFF_RED   133120    // 4096 (128 rows x 8 slots)
#define OFF_CS    137216    // 1024
#define OFF_GS    138240    // 1024
#define OFF_W2S   139264    // 1024
#define SMEM_TOTAL 140288

// W1 pre-packed fp16 hi/lo in nt-pair mma-fragment layout (u32 words):
// [chunk 8]{8192} [split 2]{4096} [kstep 2]{2048} [ntpair 16]{128} [lane 32]{4} [slot 4]
__device__ __align__(16) uint32_t g_Bpk[8 * 8192];
__device__ float g_C[HIDDEN];
__device__ float g_G[HIDDEN];
__device__ float g_W2[HIDDEN];

typedef unsigned long long u64;

__global__ void prep_w1(const float* __restrict__ W1) {
    const int k0 = blockIdx.x * 2;
    const int n  = threadIdx.x;
    float v0 = W1[k0 * 256 + n];
    float v1 = W1[(k0 + 1) * 256 + n];
    __half h0 = __float2half_rn(v0);
    __half h1 = __float2half_rn(v1);
    __half l0 = __float2half_rn(v0 - __half2float(h0));
    __half l1 = __float2half_rn(v1 - __half2float(h1));
    const int chunk = k0 >> 5;
    const int kstep = (k0 >> 4) & 1;
    const int kk    = k0 & 15;
    const int ntile = n >> 3;
    const int lane  = ((n & 7) << 2) | ((kk & 7) >> 1);
    const int reg   = (kk >> 3) & 1;
    const int pair  = ntile >> 1;
    const int slot  = (ntile & 1) * 2 + reg;
    const int base  = chunk * 8192 + kstep * 2048 + pair * 128 + lane * 4 + slot;
    __half2 hp = __halves2half2(h0, h1);
    __half2 lp = __halves2half2(l0, l1);
    g_Bpk[base]        = *(uint32_t*)&hp;     // split 0 (hi)
    g_Bpk[base + 4096] = *(uint32_t*)&lp;     // split 1 (lo)
}

__global__ void prep_cg(const float* __restrict__ W1, const float* __restrict__ gamma,
                        const float* __restrict__ beta, const float* __restrict__ b1,
                        const float* __restrict__ W2) {
    int j = threadIdx.x;
    float P = 0.f, G = 0.f;
    for (int c = 0; c < 256; c++) {
        float w = W1[c * 256 + j];
        P = fmaf(beta[c], w, P);
        G = fmaf(gamma[c], w, G);
    }
    g_C[j]  = P + b1[j];
    g_G[j]  = G;
    g_W2[j] = W2[j];
}

__device__ __forceinline__ uint32_t smem_u32(const void* p) {
    uint32_t a;
    asm("{ .reg .u64 t; cvta.to.shared.u64 t, %1; cvt.u32.u64 %0, t; }" : "=r"(a) : "l"(p));
    return a;
}
__device__ __forceinline__ uint64_t to_global(const void* p) {
    uint64_t a; asm("cvta.to.global.u64 %0, %1;" : "=l"(a) : "l"(p)); return a;
}
__device__ __forceinline__ void cp_async16(uint32_t s, uint64_t g) {
    asm volatile("cp.async.cg.shared.global [%0], [%1], 16;" :: "r"(s), "l"(g) : "memory");
}
#define CP_COMMIT() asm volatile("cp.async.commit_group;" ::: "memory")
#define CP_WAIT1()  asm volatile("cp.async.wait_group 1;" ::: "memory")
#define CP_WAIT0()  asm volatile("cp.async.wait_group 0;" ::: "memory")

#define LDS128(r, addr) \
    asm volatile("ld.shared.v4.b32 {%0,%1,%2,%3}, [%4];" \
        : "=r"((r)[0]), "=r"((r)[1]), "=r"((r)[2]), "=r"((r)[3]) : "r"(addr))

// packed f32x2 helpers
__device__ __forceinline__ u64 pk2(float lo, float hi) {
    u64 r; asm("mov.b64 %0, {%1, %2};" : "=l"(r) : "f"(lo), "f"(hi)); return r;
}
__device__ __forceinline__ void upk2(u64 v, float &lo, float &hi) {
    asm("mov.b64 {%0, %1}, %2;" : "=f"(lo), "=f"(hi) : "l"(v));
}
__device__ __forceinline__ void ffma2(u64 &d, u64 a, u64 b) {
    asm("fma.rn.f32x2 %0, %1, %2, %0;" : "+l"(d) : "l"(a), "l"(b));
}
__device__ __forceinline__ u64 fadd2(u64 a, u64 b) {
    u64 d; asm("add.rn.f32x2 %0, %1, %2;" : "=l"(d) : "l"(a), "l"(b)); return d;
}
__device__ __forceinline__ u64 fmul2(u64 a, u64 b) {
    u64 d; asm("mul.rn.f32x2 %0, %1, %2;" : "=l"(d) : "l"(a), "l"(b)); return d;
}

// fp16 inputs, fp32 accumulate
#define MMA_F32(d, a, b0, b1v) \
    asm volatile("mma.sync.aligned.m16n8k16.row.col.f32.f16.f16.f32 " \
        "{%0,%1,%2,%3}, {%4,%5,%6,%7}, {%8,%9}, {%0,%1,%2,%3};" \
        : "+f"((d)[0]), "+f"((d)[1]), "+f"((d)[2]), "+f"((d)[3]) \
        : "r"((a)[0]), "r"((a)[1]), "r"((a)[2]), "r"((a)[3]), \
          "r"(b0), "r"(b1v))

// fp16 inputs, fp16 accumulate (cross term)
#define MMA_F16(d, a, b0, b1v) \
    asm volatile("mma.sync.aligned.m16n8k16.row.col.f16.f16.f16.f16 " \
        "{%0,%1}, {%2,%3,%4,%5}, {%6,%7}, {%0,%1};" \
        : "+r"((d)[0]), "+r"((d)[1]) \
        : "r"((a)[0]), "r"((a)[1]), "r"((a)[2]), "r"((a)[3]), \
          "r"(b0), "r"(b1v))

__device__ __forceinline__ float gelu_exact(float x) {
    return 0.5f * x * (1.0f + erff(x * 0.70710678118654752440f));
}

__global__ void __launch_bounds__(TPB)
dhh_main(const float* __restrict__ final_h,
         const float* __restrict__ future_met,
         const float* __restrict__ step_q,
         const float* __restrict__ W_fm,
         const float* __restrict__ b_fm,
         const float* __restrict__ gamma,
         const float* __restrict__ b2,
         float* __restrict__ out)
{
    extern __shared__ __align__(1024) char smem[];
    float* smf = (float*)smem;
    const uint32_t sbase = smem_u32(smem);
    const int tid  = threadIdx.x;
    const int w    = tid >> 5;
    const int lane = tid & 31;

    const int b  = blockIdx.x / (N_SZ / GRP);
    const int n0 = (blockIdx.x % (N_SZ / GRP)) * GRP;

    // ---- stage phase-A inputs + persistent constants ----
    for (int i = tid; i < T_HOR * 256; i += TPB) {
        int t = i >> 8, c = i & 255;
        smf[OFF_QB / 4 + t * 258 + c] = step_q[i] + b_fm[c];
    }
    for (int i = tid; i < FMET * 256; i += TPB)
        smf[OFF_WFM / 4 + i] = W_fm[i];
    for (int i = tid; i < GRP * 256; i += TPB)
        smf[OFF_FH / 4 + i] = final_h[((size_t)b * N_SZ + n0) * 256 + i];
    for (int i = tid; i < GRP * T_HOR * FMET; i += TPB) {
        int ln = i / (T_HOR * FMET), r = i % (T_HOR * FMET);
        int t = r >> 4, f = r & 15;
        smf[OFF_FM / 4 + (ln * T_HOR + t) * FMET + f] =
            future_met[((size_t)(b * T_HOR + t) * N_SZ + (n0 + ln)) * FMET + f];
    }
    if (tid < 256) {
        smf[OFF_GAM / 4 + tid] = gamma[tid];
        smf[OFF_CS  / 4 + tid] = g_C[tid];
        smf[OFF_GS  / 4 + tid] = g_G[tid];
        smf[OFF_W2S / 4 + tid] = g_W2[tid];
    }
    __syncthreads();

    // ---- phase A: combined -> gamma-scaled fp16 hi fragments (packed f32x2 math) ----
    {
        const int m = tid & 127, half = tid >> 7;
        int ln = m / 24; if (ln > 4) ln = 4;
        const int t = m % 24;
        u64 fmv2[FMET];
#pragma unroll
        for (int f = 0; f < FMET; f++) {
            float v = smf[OFF_FM / 4 + (ln * T_HOR + t) * FMET + f];
            fmv2[f] = pk2(v, v);
        }

        u64 accS = 0ull, accS2 = 0ull;
        const int cb = half * 128;
        const uint32_t mbase = (uint32_t)(m >> 4) * 16;
        const uint32_t lane_m = (uint32_t)(m & 7) << 2;
        const uint32_t reg_m  = ((m & 15) >= 8) ? 1u : 0u;
        const u64* qbp = (const u64*)&smf[OFF_QB / 4 + t * 258 + cb];
        const u64* fhp = (const u64*)&smf[OFF_FH / 4 + ln * 256 + cb];
        const u64* gmp = (const u64*)&smf[OFF_GAM / 4 + cb];
#pragma unroll 4
        for (int i = 0; i < 64; i++) {
            const int c = cb + 2 * i;
            u64 v = fadd2(qbp[i], fhp[i]);
#pragma unroll
            for (int f = 0; f < FMET; f++) {
                const u64 wf = *(const u64*)&smf[OFF_WFM / 4 + f * 256 + c];
                ffma2(v, fmv2[f], wf);
            }
            accS = fadd2(accS, v);
            ffma2(accS2, v, v);
            u64 a = fmul2(v, gmp[i]);
            float a0, a1; upk2(a, a0, a1);
            __half2 hp = __floats2half2_rn(a0, a1);

            const uint32_t kk   = (uint32_t)(c & 15);
            const uint32_t lnA  = lane_m | ((kk & 7) >> 1);
            const uint32_t reg  = ((kk & 8) ? 2u : 0u) | reg_m;
            uint32_t off = ((mbase + (uint32_t)(c >> 4)) << 9) + (lnA << 4) + (reg << 2);
            off ^= (off >> 2) & 0x60;
            *(uint32_t*)(smem + OFF_AHI + off) = *(uint32_t*)&hp;
        }
        float sl, sh, s2l, s2h;
        upk2(accS, sl, sh);
        upk2(accS2, s2l, s2h);
        smf[OFF_STS  / 4 + m * 2 + half] = sl + sh;
        smf[OFF_STS2 / 4 + m * 2 + half] = s2l + s2h;
    }
    __syncthreads();

    // ---- GEMM: 8 k32-chunks; Ahi*Bhi in f32 acc, Ahi*Blo in f16 acc ----
    const int wm = w & 3, wn = w >> 2;
    float acc0[16][4], acc1[16][4];
    uint32_t cr0[16][2], cr1[16][2];
#pragma unroll
    for (int nt = 0; nt < 16; nt++) {
#pragma unroll
        for (int e = 0; e < 4; e++) { acc0[nt][e] = 0.f; acc1[nt][e] = 0.f; }
        cr0[nt][0] = 0u; cr0[nt][1] = 0u;
        cr1[nt][0] = 0u; cr1[nt][1] = 0u;
    }

    const uint32_t laneOff = ((uint32_t)lane << 4) ^ (((uint32_t)lane & 0x18) << 2);
    const uint64_t gB = to_global(g_Bpk);

    // prefetch chunk 0 (hi+lo, 32KB)
    {
        uint32_t d = sbase + OFF_B + tid * 16;
        uint64_t s = gB + tid * 16;
#pragma unroll
        for (int i = 0; i < 8; i++) cp_async16(d + i * 4096, s + i * 4096);
        CP_COMMIT();
    }

    for (int c = 0; c < 8; c++) {
        if (c < 7) {
            uint32_t d = sbase + OFF_B + ((c + 1) & 1) * 32768 + tid * 16;
            uint64_t s = gB + (size_t)(c + 1) * 32768 + tid * 16;
#pragma unroll
            for (int i = 0; i < 8; i++) cp_async16(d + i * 4096, s + i * 4096);
            CP_COMMIT();
            CP_WAIT1();
        } else {
            CP_WAIT0();
        }
        __syncthreads();

        const uint32_t bufB = sbase + OFF_B + (uint32_t)(c & 1) * 32768;
#pragma unroll
        for (int kl = 0; kl < 2; kl++) {
            const uint32_t ks = (uint32_t)(c * 2 + kl);
            uint32_t ah0[4], ah1[4];
            const uint32_t aRow0 = (((uint32_t)(wm * 2 + 0) * 16 + ks) << 9) + laneOff;
            const uint32_t aRow1 = (((uint32_t)(wm * 2 + 1) * 16 + ks) << 9) + laneOff;
            LDS128(ah0, sbase + OFF_AHI + aRow0);
            LDS128(ah1, sbase + OFF_AHI + aRow1);

            const uint32_t bHi = bufB + (uint32_t)kl * 8192 +
                                 (uint32_t)(wn * 8) * 512 + (uint32_t)lane * 16;
            const uint32_t bLo = bHi + 16384;
#pragma unroll
            for (int p = 0; p < 8; p++) {
                uint32_t bh[4], bl[4];
                LDS128(bh, bHi + p * 512);
                LDS128(bl, bLo + p * 512);
                const int nte = 2 * p, nto = 2 * p + 1;
                MMA_F32(acc0[nte], ah0, bh[0], bh[1]);
                MMA_F32(acc1[nte], ah1, bh[0], bh[1]);
                MMA_F32(acc0[nto], ah0, bh[2], bh[3]);
                MMA_F32(acc1[nto], ah1, bh[2], bh[3]);
                MMA_F16(cr0[nte], ah0, bl[0], bl[1]);
                MMA_F16(cr1[nte], ah1, bl[0], bl[1]);
                MMA_F16(cr0[nto], ah0, bl[2], bl[3]);
                MMA_F16(cr1[nto], ah1, bl[2], bl[3]);
            }
        }
        __syncthreads();
    }

    // ---- epilogue: LN fold + exact GELU + W2 dot ----
    {
        const int g = lane >> 2;
        float rstd[4], mr[4];
#pragma unroll
        for (int q = 0; q < 4; q++) {
            const int row = wm * 32 + q * 8 + g;
            const float ssum = smf[OFF_STS / 4 + row * 2] + smf[OFF_STS / 4 + row * 2 + 1];
            const float q2   = smf[OFF_STS2 / 4 + row * 2] + smf[OFF_STS2 / 4 + row * 2 + 1];
            const float mu   = ssum * (1.0f / HIDDEN);
            const float var  = q2 * (1.0f / HIDDEN) - mu * mu;
            rstd[q] = rsqrtf(var + EPS_LN);
            mr[q]   = mu * rstd[q];
        }
        float part[4] = {0.f, 0.f, 0.f, 0.f};
#pragma unroll
        for (int nt = 0; nt < 16; nt++) {
            float2 cx[4];
            cx[0] = __half22float2(*(__half2*)&cr0[nt][0]);
            cx[1] = __half22float2(*(__half2*)&cr0[nt][1]);
            cx[2] = __half22float2(*(__half2*)&cr1[nt][0]);
            cx[3] = __half22float2(*(__half2*)&cr1[nt][1]);
#pragma unroll
            for (int e = 0; e < 2; e++) {
                const int j = (wn * 16 + nt) * 8 + (lane & 3) * 2 + e;
                const float csj = smf[OFF_CS / 4 + j];
                const float gsj = smf[OFF_GS / 4 + j];
                const float w2j = smf[OFF_W2S / 4 + j];
#pragma unroll
                for (int q = 0; q < 4; q++) {
                    const float base = (q < 2) ? acc0[nt][(q & 1) * 2 + e]
                                               : acc1[nt][(q & 1) * 2 + e];
                    const float2 cpair = cx[(q < 2 ? 0 : 2) + (q & 1)];
                    const float S = base + (e ? cpair.y : cpair.x);
                    const float o = fmaf(rstd[q], S, csj) - mr[q] * gsj;
                    part[q] = fmaf(gelu_exact(o), w2j, part[q]);
                }
            }
        }
        const int slot = ((lane & 3) << 1) | wn;
#pragma unroll
        for (int q = 0; q < 4; q++) {
            const int row = wm * 32 + q * 8 + g;
            smf[OFF_RED / 4 + row * 8 + slot] = part[q];
        }
    }
    __syncthreads();

    if (tid < GRP * T_HOR) {
        const int ln = tid / T_HOR, t = tid % T_HOR;
        const float* rr = &smf[OFF_RED / 4 + tid * 8];
        float s = rr[0] + rr[1] + rr[2] + rr[3] + rr[4] + rr[5] + rr[6] + rr[7];
        out[(size_t)(b * T_HOR + t) * N_SZ + (n0 + ln)] = s + b2[0];
    }
}

extern "C" void kernel_launch(void* const* d_in, const int* in_sizes, int n_in,
                              void* d_out, int out_size) {
    const float* final_h    = (const float*)d_in[0];
    const float* future_met = (const float*)d_in[1];
    const float* step_q     = (const float*)d_in[2];
    const float* W_fm       = (const float*)d_in[3];
    const float* b_fm       = (const float*)d_in[4];
    const float* gamma      = (const float*)d_in[5];
    const float* beta       = (const float*)d_in[6];
    const float* W1         = (const float*)d_in[7];
    const float* b1         = (const float*)d_in[8];
    const float* W2         = (const float*)d_in[9];
    const float* b2         = (const float*)d_in[10];
    float* out = (float*)d_out;

    prep_w1<<<128, 256>>>(W1);
    prep_cg<<<1, 256>>>(W1, gamma, beta, b1, W2);

    cudaFuncSetAttribute(dhh_main, cudaFuncAttributeMaxDynamicSharedMemorySize, SMEM_TOTAL);
    dhh_main<<<NCTA, TPB, SMEM_TOTAL>>>(final_h, future_met, step_q, W_fm, b_fm,
                                        gamma, b2, out);
}

// round 7
// speedup vs baseline: 1.5782x; 1.2809x over previous
#include <cuda_runtime.h>
#include <cuda_fp16.h>
#include <math.h>
#include <stdint.h>

#define HIDDEN 256
#define T_HOR  24
#define FMET   16
#define B_SZ   16
#define N_SZ   1000
#define GRP    5
#define TPB    256
#define NCTA   (B_SZ * (N_SZ / GRP))   // 3200
#define EPS_LN 1e-5f

// ---- smem layout (bytes) ----
#define OFF_AHI   0         // A hi fragments, 64KB
#define OFF_B     65536     // B double buffer, 2 x 16KB -> 98304
// staging (dead after phase A)
#define OFF_QB    98304     // 24*258*4 = 24768 -> 123072
#define OFF_WFM2  123072    // u64[2048] = 16384 -> 139456
#define OFF_FH    139456    // 5120 -> 144576
#define OFF_FM    144576    // 7680 -> 152256
#define OFF_GAM   152256    // 1024 -> 153280
// persistent
#define OFF_STS   153280    // 1024
#define OFF_STS2  154304    // 1024
#define OFF_RED   155328    // 8192 (128 rows x 16 slots)
#define OFF_CS    163520    // 1024
#define OFF_GS    164544    // 1024
#define OFF_W2S   165568    // 1024
#define SMEM_TOTAL 166592

// W1 hi-only, fragment-packed (u32):
// [chunk 8]{4096} [kstep 2]{2048} [ntpair 16]{128} [lane 32]{4} [slot 4]
__device__ __align__(16) uint32_t g_Bpk[8 * 4096];
__device__ float g_C[HIDDEN];
__device__ float g_G[HIDDEN];
__device__ float g_W2[HIDDEN];

typedef unsigned long long u64;

__global__ void prep_w1(const float* __restrict__ W1) {
    const int k0 = blockIdx.x * 2;
    const int n  = threadIdx.x;
    float v0 = W1[k0 * 256 + n];
    float v1 = W1[(k0 + 1) * 256 + n];
    __half2 hp = __floats2half2_rn(v0, v1);
    const int chunk = k0 >> 5;
    const int kstep = (k0 >> 4) & 1;
    const int kk    = k0 & 15;
    const int ntile = n >> 3;
    const int lane  = ((n & 7) << 2) | ((kk & 7) >> 1);
    const int reg   = (kk >> 3) & 1;
    const int pair  = ntile >> 1;
    const int slot  = (ntile & 1) * 2 + reg;
    g_Bpk[chunk * 4096 + kstep * 2048 + pair * 128 + lane * 4 + slot] = *(uint32_t*)&hp;
}

__global__ void prep_cg(const float* __restrict__ W1, const float* __restrict__ gamma,
                        const float* __restrict__ beta, const float* __restrict__ b1,
                        const float* __restrict__ W2) {
    int j = threadIdx.x;
    float P = 0.f, G = 0.f;
    for (int c = 0; c < 256; c++) {
        float w = W1[c * 256 + j];
        P = fmaf(beta[c], w, P);
        G = fmaf(gamma[c], w, G);
    }
    g_C[j]  = P + b1[j];
    g_G[j]  = G;
    g_W2[j] = W2[j];
}

__device__ __forceinline__ uint32_t smem_u32(const void* p) {
    uint32_t a;
    asm("{ .reg .u64 t; cvta.to.shared.u64 t, %1; cvt.u32.u64 %0, t; }" : "=r"(a) : "l"(p));
    return a;
}
__device__ __forceinline__ uint64_t to_global(const void* p) {
    uint64_t a; asm("cvta.to.global.u64 %0, %1;" : "=l"(a) : "l"(p)); return a;
}
__device__ __forceinline__ void cp_async16(uint32_t s, uint64_t g) {
    asm volatile("cp.async.cg.shared.global [%0], [%1], 16;" :: "r"(s), "l"(g) : "memory");
}
#define CP_COMMIT() asm volatile("cp.async.commit_group;" ::: "memory")
#define CP_WAIT1()  asm volatile("cp.async.wait_group 1;" ::: "memory")
#define CP_WAIT0()  asm volatile("cp.async.wait_group 0;" ::: "memory")

#define LDS128(r, addr) \
    asm volatile("ld.shared.v4.b32 {%0,%1,%2,%3}, [%4];" \
        : "=r"((r)[0]), "=r"((r)[1]), "=r"((r)[2]), "=r"((r)[3]) : "r"(addr))

// packed f32x2 helpers
__device__ __forceinline__ u64 pk2(float lo, float hi) {
    u64 r; asm("mov.b64 %0, {%1, %2};" : "=l"(r) : "f"(lo), "f"(hi)); return r;
}
__device__ __forceinline__ void upk2(u64 v, float &lo, float &hi) {
    asm("mov.b64 {%0, %1}, %2;" : "=f"(lo), "=f"(hi) : "l"(v));
}
__device__ __forceinline__ void ffma2(u64 &d, u64 a, u64 b) {
    asm("fma.rn.f32x2 %0, %1, %2, %0;" : "+l"(d) : "l"(a), "l"(b));
}
__device__ __forceinline__ u64 fadd2(u64 a, u64 b) {
    u64 d; asm("add.rn.f32x2 %0, %1, %2;" : "=l"(d) : "l"(a), "l"(b)); return d;
}
__device__ __forceinline__ u64 fmul2(u64 a, u64 b) {
    u64 d; asm("mul.rn.f32x2 %0, %1, %2;" : "=l"(d) : "l"(a), "l"(b)); return d;
}

// fp16 inputs, fp32 accumulate
#define MMA_F32(d, a, b0, b1v) \
    asm volatile("mma.sync.aligned.m16n8k16.row.col.f32.f16.f16.f32 " \
        "{%0,%1,%2,%3}, {%4,%5,%6,%7}, {%8,%9}, {%0,%1,%2,%3};" \
        : "+f"((d)[0]), "+f"((d)[1]), "+f"((d)[2]), "+f"((d)[3]) \
        : "r"((a)[0]), "r"((a)[1]), "r"((a)[2]), "r"((a)[3]), \
          "r"(b0), "r"(b1v))

__device__ __forceinline__ float gelu_exact(float x) {
    return 0.5f * x * (1.0f + erff(x * 0.70710678118654752440f));
}

__global__ void __launch_bounds__(TPB)
dhh_main(const float* __restrict__ final_h,
         const float* __restrict__ future_met,
         const float* __restrict__ step_q,
         const float* __restrict__ W_fm,
         const float* __restrict__ b_fm,
         const float* __restrict__ gamma,
         const float* __restrict__ b2,
         float* __restrict__ out)
{
    extern __shared__ __align__(1024) char smem[];
    float* smf = (float*)smem;
    const uint32_t sbase = smem_u32(smem);
    const int tid  = threadIdx.x;
    const int w    = tid >> 5;
    const int lane = tid & 31;

    const int b  = blockIdx.x / (N_SZ / GRP);
    const int n0 = (blockIdx.x % (N_SZ / GRP)) * GRP;

    const uint64_t gB = to_global(g_Bpk);

    // ---- prefetch B chunk 0 immediately (hides under staging + phase A) ----
    {
        uint32_t d = sbase + OFF_B + tid * 16;
        uint64_t s = gB + tid * 16;
#pragma unroll
        for (int i = 0; i < 4; i++) cp_async16(d + i * 4096, s + i * 4096);
        CP_COMMIT();
    }

    // ---- stage phase-A inputs + persistent constants ----
    for (int i = tid; i < T_HOR * 256; i += TPB) {
        int t = i >> 8, c = i & 255;
        smf[OFF_QB / 4 + t * 258 + c] = step_q[i] + b_fm[c];
    }
    // W_fm repacked as f32x2 pairs: wfm2[cp*16 + f] = (W_fm[f][2cp], W_fm[f][2cp+1])
    {
        u64* wfm2 = (u64*)(smem + OFF_WFM2);
        for (int i = tid; i < 2048; i += TPB) {
            int f  = i >> 7;
            int cp = i & 127;
            float2 wv = *(const float2*)&W_fm[f * 256 + 2 * cp];
            wfm2[cp * 16 + f] = pk2(wv.x, wv.y);
        }
    }
    for (int i = tid; i < GRP * 256; i += TPB)
        smf[OFF_FH / 4 + i] = final_h[((size_t)b * N_SZ + n0) * 256 + i];
    for (int i = tid; i < GRP * T_HOR * FMET; i += TPB) {
        int ln = i / (T_HOR * FMET), r = i % (T_HOR * FMET);
        int t = r >> 4, f = r & 15;
        smf[OFF_FM / 4 + (ln * T_HOR + t) * FMET + f] =
            future_met[((size_t)(b * T_HOR + t) * N_SZ + (n0 + ln)) * FMET + f];
    }
    if (tid < 256) {
        smf[OFF_GAM / 4 + tid] = gamma[tid];
        smf[OFF_CS  / 4 + tid] = g_C[tid];
        smf[OFF_GS  / 4 + tid] = g_G[tid];
        smf[OFF_W2S / 4 + tid] = g_W2[tid];
    }
    __syncthreads();

    // ---- phase A: combined -> gamma-scaled fp16 hi fragments ----
    {
        const int m = tid & 127, half = tid >> 7;
        int ln = m / 24; if (ln > 4) ln = 4;
        const int t = m % 24;
        u64 fmv2[FMET];
#pragma unroll
        for (int f = 0; f < FMET; f++) {
            float v = smf[OFF_FM / 4 + (ln * T_HOR + t) * FMET + f];
            fmv2[f] = pk2(v, v);
        }

        u64 accS = 0ull, accS2 = 0ull;
        const int cb = half * 128;
        const uint32_t mbase = (uint32_t)(m >> 4) * 16;
        const uint32_t lane_m = (uint32_t)(m & 7) << 2;
        const uint32_t reg_m  = ((m & 15) >= 8) ? 1u : 0u;
        const u64* qbp = (const u64*)&smf[OFF_QB / 4 + t * 258 + cb];
        const u64* fhp = (const u64*)&smf[OFF_FH / 4 + ln * 256 + cb];
        const u64* gmp = (const u64*)&smf[OFF_GAM / 4 + cb];
        const u64* wfm2 = (const u64*)(smem + OFF_WFM2);
#pragma unroll 4
        for (int i = 0; i < 64; i++) {
            const int c  = cb + 2 * i;
            const int cp = half * 64 + i;
            u64 v = fadd2(qbp[i], fhp[i]);
            const ulonglong2* wfp = (const ulonglong2*)&wfm2[cp * 16];
#pragma unroll
            for (int f8 = 0; f8 < 8; f8++) {
                ulonglong2 wp = wfp[f8];
                ffma2(v, fmv2[2 * f8],     wp.x);
                ffma2(v, fmv2[2 * f8 + 1], wp.y);
            }
            accS = fadd2(accS, v);
            ffma2(accS2, v, v);
            u64 a = fmul2(v, gmp[i]);
            float a0, a1; upk2(a, a0, a1);
            __half2 hp = __floats2half2_rn(a0, a1);

            const uint32_t kk   = (uint32_t)(c & 15);
            const uint32_t lnA  = lane_m | ((kk & 7) >> 1);
            const uint32_t reg  = ((kk & 8) ? 2u : 0u) | reg_m;
            uint32_t off = ((mbase + (uint32_t)(c >> 4)) << 9) + (lnA << 4) + (reg << 2);
            off ^= (off >> 2) & 0x60;
            *(uint32_t*)(smem + OFF_AHI + off) = *(uint32_t*)&hp;
        }
        float sl, sh, s2l, s2h;
        upk2(accS, sl, sh);
        upk2(accS2, s2l, s2h);
        smf[OFF_STS  / 4 + m * 2 + half] = sl + sh;
        smf[OFF_STS2 / 4 + m * 2 + half] = s2l + s2h;
    }
    __syncthreads();

    // ---- GEMM: 8 k32-chunks, hi*hi only; warp grid wm(2) x wn(4) ----
    const int wm = w & 1, wn = w >> 1;
    float acc[4][8][4];
#pragma unroll
    for (int mt = 0; mt < 4; mt++)
#pragma unroll
        for (int nt = 0; nt < 8; nt++)
#pragma unroll
            for (int e = 0; e < 4; e++) acc[mt][nt][e] = 0.f;

    const uint32_t laneOff = ((uint32_t)lane << 4) ^ (((uint32_t)lane & 0x18) << 2);

    for (int c = 0; c < 8; c++) {
        if (c < 7) {
            uint32_t d = sbase + OFF_B + ((c + 1) & 1) * 16384 + tid * 16;
            uint64_t s = gB + (size_t)(c + 1) * 16384 + tid * 16;
#pragma unroll
            for (int i = 0; i < 4; i++) cp_async16(d + i * 4096, s + i * 4096);
            CP_COMMIT();
            CP_WAIT1();
        } else {
            CP_WAIT0();
        }
        __syncthreads();

        const uint32_t bufB = sbase + OFF_B + (uint32_t)(c & 1) * 16384;
#pragma unroll
        for (int kl = 0; kl < 2; kl++) {
            const uint32_t ks = (uint32_t)(c * 2 + kl);
            uint32_t ah[4][4];
#pragma unroll
            for (int mt = 0; mt < 4; mt++) {
                const uint32_t aRow = (((uint32_t)((wm * 4 + mt) * 16 + ks)) << 9) + laneOff;
                LDS128(ah[mt], sbase + OFF_AHI + aRow);
            }
            uint32_t bh[4][4];
            const uint32_t bBase = bufB + (uint32_t)kl * 8192 +
                                   (uint32_t)wn * 2048 + (uint32_t)lane * 16;
#pragma unroll
            for (int p = 0; p < 4; p++) LDS128(bh[p], bBase + p * 512);
#pragma unroll
            for (int mt = 0; mt < 4; mt++)
#pragma unroll
                for (int p = 0; p < 4; p++) {
                    MMA_F32(acc[mt][2 * p],     ah[mt], bh[p][0], bh[p][1]);
                    MMA_F32(acc[mt][2 * p + 1], ah[mt], bh[p][2], bh[p][3]);
                }
        }
        __syncthreads();
    }

    // ---- epilogue: LN fold + exact GELU + W2 dot ----
    {
        const int g = lane >> 2, cq = lane & 3;
        float rstd[8], mr[8];
#pragma unroll
        for (int idx = 0; idx < 8; idx++) {
            const int row = wm * 64 + (idx >> 1) * 16 + (idx & 1) * 8 + g;
            const float ssum = smf[OFF_STS / 4 + row * 2] + smf[OFF_STS / 4 + row * 2 + 1];
            const float q2   = smf[OFF_STS2 / 4 + row * 2] + smf[OFF_STS2 / 4 + row * 2 + 1];
            const float mu   = ssum * (1.0f / HIDDEN);
            const float var  = q2 * (1.0f / HIDDEN) - mu * mu;
            rstd[idx] = rsqrtf(var + EPS_LN);
            mr[idx]   = mu * rstd[idx];
        }
        float part[8] = {0.f, 0.f, 0.f, 0.f, 0.f, 0.f, 0.f, 0.f};
#pragma unroll
        for (int mt = 0; mt < 4; mt++)
#pragma unroll
            for (int nt = 0; nt < 8; nt++) {
                const int j = wn * 64 + nt * 8 + cq * 2;
                const float cs0 = smf[OFF_CS / 4 + j],  cs1 = smf[OFF_CS / 4 + j + 1];
                const float gs0 = smf[OFF_GS / 4 + j],  gs1 = smf[OFF_GS / 4 + j + 1];
                const float w20 = smf[OFF_W2S / 4 + j], w21 = smf[OFF_W2S / 4 + j + 1];
#pragma unroll
                for (int q = 0; q < 2; q++) {
                    const int idx = mt * 2 + q;
                    const float o0 = fmaf(rstd[idx], acc[mt][nt][q * 2 + 0],
                                          fmaf(-mr[idx], gs0, cs0));
                    const float o1 = fmaf(rstd[idx], acc[mt][nt][q * 2 + 1],
                                          fmaf(-mr[idx], gs1, cs1));
                    part[idx] = fmaf(gelu_exact(o0), w20, part[idx]);
                    part[idx] = fmaf(gelu_exact(o1), w21, part[idx]);
                }
            }
#pragma unroll
        for (int idx = 0; idx < 8; idx++) {
            const int row = wm * 64 + (idx >> 1) * 16 + (idx & 1) * 8 + g;
            smf[OFF_RED / 4 + row * 16 + wn * 4 + cq] = part[idx];
        }
    }
    __syncthreads();

    if (tid < GRP * T_HOR) {
        const int ln = tid / T_HOR, t = tid % T_HOR;
        const float4* rr = (const float4*)&smf[OFF_RED / 4 + tid * 16];
        float4 r0 = rr[0], r1 = rr[1], r2 = rr[2], r3 = rr[3];
        float s = ((r0.x + r0.y) + (r0.z + r0.w)) + ((r1.x + r1.y) + (r1.z + r1.w)) +
                  ((r2.x + r2.y) + (r2.z + r2.w)) + ((r3.x + r3.y) + (r3.z + r3.w));
        out[(size_t)(b * T_HOR + t) * N_SZ + (n0 + ln)] = s + b2[0];
    }
}

extern "C" void kernel_launch(void* const* d_in, const int* in_sizes, int n_in,
                              void* d_out, int out_size) {
    const float* final_h    = (const float*)d_in[0];
    const float* future_met = (const float*)d_in[1];
    const float* step_q     = (const float*)d_in[2];
    const float* W_fm       = (const float*)d_in[3];
    const float* b_fm       = (const float*)d_in[4];
    const float* gamma      = (const float*)d_in[5];
    const float* beta       = (const float*)d_in[6];
    const float* W1         = (const float*)d_in[7];
    const float* b1         = (const float*)d_in[8];
    const float* W2         = (const float*)d_in[9];
    const float* b2         = (const float*)d_in[10];
    float* out = (float*)d_out;

    prep_w1<<<128, 256>>>(W1);
    prep_cg<<<1, 256>>>(W1, gamma, beta, b1, W2);

    cudaFuncSetAttribute(dhh_main, cudaFuncAttributeMaxDynamicSharedMemorySize, SMEM_TOTAL);
    dhh_main<<<NCTA, TPB, SMEM_TOTAL>>>(final_h, future_met, step_q, W_fm, b_fm,
                                        gamma, b2, out);
}

// round 8
// speedup vs baseline: 2.0613x; 1.3061x over previous
#include <cuda_runtime.h>
#include <cuda_fp16.h>
#include <math.h>
#include <stdint.h>

#define HIDDEN 256
#define T_HOR  24
#define FMET   16
#define B_SZ   16
#define N_SZ   1000
#define GRP    5
#define TPB    256
#define NCTA   (B_SZ * (N_SZ / GRP))   // 3200
#define EPS_LN 1e-5f

// ---- smem layout (bytes) ----
#define OFF_AHI   0         // A hi fragments, 64KB
#define OFF_QBH   65536     // step_q as half2, 24 x 129 x 4B = 12384 -> pad 12416
#define OFF_WFM2  77952     // W_fm f32x2 pairs, 16384
#define OFF_FH    94336     // (final_h + b_fm), 5 x 260 x 4 = 5200 -> pad 5248
#define OFF_GAM   99584     // 1024
#define OFF_STS   100608    // 1024
#define OFF_STS2  101632    // 1024
#define OFF_RED   102656    // 8192 (128 rows x 16 slots)
#define OFF_CS    110848    // 1024
#define OFF_GS    111872    // 1024
#define OFF_W2S   112896    // 1024
#define SMEM_TOTAL 113920   // x2 CTAs = 227840 <= 228KB

// W1 hi-only, fragment-packed for direct LDG (u32):
// [kstep 16]{2048} [ntpair 16]{128} [lane 32]{4} [slot 4]   slot=(nt&1)*2+reg
__device__ __align__(16) uint32_t g_Bpk[16 * 2048];
__device__ float g_C[HIDDEN];
__device__ float g_G[HIDDEN];
__device__ float g_W2[HIDDEN];

typedef unsigned long long u64;

__global__ void prep_w1(const float* __restrict__ W1) {
    const int k0 = blockIdx.x * 2;
    const int n  = threadIdx.x;
    float v0 = W1[k0 * 256 + n];
    float v1 = W1[(k0 + 1) * 256 + n];
    __half2 hp = __floats2half2_rn(v0, v1);
    const int ks    = k0 >> 4;
    const int kk    = k0 & 15;
    const int ntile = n >> 3;
    const int lane  = ((n & 7) << 2) | ((kk & 7) >> 1);
    const int reg   = (kk >> 3) & 1;
    const int pair  = ntile >> 1;
    const int slot  = (ntile & 1) * 2 + reg;
    g_Bpk[ks * 2048 + pair * 128 + lane * 4 + slot] = *(uint32_t*)&hp;
}

__global__ void prep_cg(const float* __restrict__ W1, const float* __restrict__ gamma,
                        const float* __restrict__ beta, const float* __restrict__ b1,
                        const float* __restrict__ W2) {
    int j = threadIdx.x;
    float P = 0.f, G = 0.f;
    for (int c = 0; c < 256; c++) {
        float w = W1[c * 256 + j];
        P = fmaf(beta[c], w, P);
        G = fmaf(gamma[c], w, G);
    }
    g_C[j]  = P + b1[j];
    g_G[j]  = G;
    g_W2[j] = W2[j];
}

__device__ __forceinline__ uint32_t smem_u32(const void* p) {
    uint32_t a;
    asm("{ .reg .u64 t; cvta.to.shared.u64 t, %1; cvt.u32.u64 %0, t; }" : "=r"(a) : "l"(p));
    return a;
}

#define LDS128(r, addr) \
    asm volatile("ld.shared.v4.b32 {%0,%1,%2,%3}, [%4];" \
        : "=r"((r)[0]), "=r"((r)[1]), "=r"((r)[2]), "=r"((r)[3]) : "r"(addr))

// packed f32x2 helpers
__device__ __forceinline__ u64 pk2(float lo, float hi) {
    u64 r; asm("mov.b64 %0, {%1, %2};" : "=l"(r) : "f"(lo), "f"(hi)); return r;
}
__device__ __forceinline__ void upk2(u64 v, float &lo, float &hi) {
    asm("mov.b64 {%0, %1}, %2;" : "=f"(lo), "=f"(hi) : "l"(v));
}
__device__ __forceinline__ void ffma2(u64 &d, u64 a, u64 b) {
    asm("fma.rn.f32x2 %0, %1, %2, %0;" : "+l"(d) : "l"(a), "l"(b));
}
__device__ __forceinline__ u64 fadd2(u64 a, u64 b) {
    u64 d; asm("add.rn.f32x2 %0, %1, %2;" : "=l"(d) : "l"(a), "l"(b)); return d;
}
__device__ __forceinline__ u64 fmul2(u64 a, u64 b) {
    u64 d; asm("mul.rn.f32x2 %0, %1, %2;" : "=l"(d) : "l"(a), "l"(b)); return d;
}

// fp16 inputs, fp32 accumulate
#define MMA_F32(d, a, b0, b1v) \
    asm volatile("mma.sync.aligned.m16n8k16.row.col.f32.f16.f16.f32 " \
        "{%0,%1,%2,%3}, {%4,%5,%6,%7}, {%8,%9}, {%0,%1,%2,%3};" \
        : "+f"((d)[0]), "+f"((d)[1]), "+f"((d)[2]), "+f"((d)[3]) \
        : "r"((a)[0]), "r"((a)[1]), "r"((a)[2]), "r"((a)[3]), \
          "r"(b0), "r"(b1v))

__device__ __forceinline__ float gelu_exact(float x) {
    return 0.5f * x * (1.0f + erff(x * 0.70710678118654752440f));
}

__global__ void __launch_bounds__(TPB, 2)
dhh_main(const float* __restrict__ final_h,
         const float* __restrict__ future_met,
         const float* __restrict__ step_q,
         const float* __restrict__ W_fm,
         const float* __restrict__ b_fm,
         const float* __restrict__ gamma,
         const float* __restrict__ b2,
         float* __restrict__ out)
{
    extern __shared__ __align__(1024) char smem[];
    float* smf = (float*)smem;
    const uint32_t sbase = smem_u32(smem);
    const int tid  = threadIdx.x;
    const int w    = tid >> 5;
    const int lane = tid & 31;

    const int b  = blockIdx.x / (N_SZ / GRP);
    const int n0 = (blockIdx.x % (N_SZ / GRP)) * GRP;

    // phase-A identity for this thread (needed for early fm load)
    const int m = tid & 127, half = tid >> 7;
    int ln = m / 24; if (ln > 4) ln = 4;
    const int t = m % 24;

    // ---- early LDG: this thread's future_met row (16 floats), hides under staging ----
    float4 fm0, fm1, fm2, fm3;
    {
        const float4* fmp = (const float4*)&future_met[
            ((size_t)(b * T_HOR + t) * N_SZ + (n0 + ln)) * FMET];
        fm0 = fmp[0]; fm1 = fmp[1]; fm2 = fmp[2]; fm3 = fmp[3];
    }

    // ---- stage inputs + persistent constants ----
    // step_q as half2, row stride 129 half2 (conflict-free across t)
    for (int i = tid; i < T_HOR * 128; i += TPB) {
        int tt = i >> 7, cp = i & 127;
        float2 qv = *(const float2*)&step_q[tt * 256 + 2 * cp];
        ((__half2*)(smem + OFF_QBH))[tt * 129 + cp] = __floats2half2_rn(qv.x, qv.y);
    }
    // W_fm repacked as f32x2 pairs
    {
        u64* wfm2 = (u64*)(smem + OFF_WFM2);
        for (int i = tid; i < 2048; i += TPB) {
            int f  = i >> 7;
            int cp = i & 127;
            float2 wv = *(const float2*)&W_fm[f * 256 + 2 * cp];
            wfm2[cp * 16 + f] = pk2(wv.x, wv.y);
        }
    }
    // final_h + b_fm (stride 260 floats, conflict-free across ln)
    for (int i = tid; i < GRP * 256; i += TPB) {
        int lni = i >> 8, c = i & 255;
        smf[OFF_FH / 4 + lni * 260 + c] =
            final_h[((size_t)b * N_SZ + n0) * 256 + i] + b_fm[c];
    }
    if (tid < 256) {
        smf[OFF_GAM / 4 + tid] = gamma[tid];
        smf[OFF_CS  / 4 + tid] = g_C[tid];
        smf[OFF_GS  / 4 + tid] = g_G[tid];
        smf[OFF_W2S / 4 + tid] = g_W2[tid];
    }
    __syncthreads();

    // ---- phase A: combined -> gamma-scaled fp16 hi fragments ----
    {
        u64 fmv2[FMET];
        {
            const float fv[16] = {fm0.x, fm0.y, fm0.z, fm0.w, fm1.x, fm1.y, fm1.z, fm1.w,
                                  fm2.x, fm2.y, fm2.z, fm2.w, fm3.x, fm3.y, fm3.z, fm3.w};
#pragma unroll
            for (int f = 0; f < FMET; f++) fmv2[f] = pk2(fv[f], fv[f]);
        }

        u64 accS = 0ull, accS2 = 0ull;
        const int cb = half * 128;
        const uint32_t mbase = (uint32_t)(m >> 4) * 16;
        const uint32_t lane_m = (uint32_t)(m & 7) << 2;
        const uint32_t reg_m  = ((m & 15) >= 8) ? 1u : 0u;
        const __half2* qbp = (const __half2*)(smem + OFF_QBH) + t * 129 + half * 64;
        const u64* fhp  = (const u64*)&smf[OFF_FH / 4 + ln * 260 + cb];
        const u64* gmp  = (const u64*)&smf[OFF_GAM / 4 + cb];
        const u64* wfm2 = (const u64*)(smem + OFF_WFM2);
#pragma unroll 4
        for (int i = 0; i < 64; i++) {
            const int c  = cb + 2 * i;
            const int cp = half * 64 + i;
            float2 qf = __half22float2(qbp[i]);
            u64 v = fadd2(pk2(qf.x, qf.y), fhp[i]);
            const ulonglong2* wfp = (const ulonglong2*)&wfm2[cp * 16];
#pragma unroll
            for (int f8 = 0; f8 < 8; f8++) {
                ulonglong2 wp = wfp[f8];
                ffma2(v, fmv2[2 * f8],     wp.x);
                ffma2(v, fmv2[2 * f8 + 1], wp.y);
            }
            accS = fadd2(accS, v);
            ffma2(accS2, v, v);
            u64 a = fmul2(v, gmp[i]);
            float a0, a1; upk2(a, a0, a1);
            __half2 hp = __floats2half2_rn(a0, a1);

            const uint32_t kk   = (uint32_t)(c & 15);
            const uint32_t lnA  = lane_m | ((kk & 7) >> 1);
            const uint32_t reg  = ((kk & 8) ? 2u : 0u) | reg_m;
            uint32_t off = ((mbase + (uint32_t)(c >> 4)) << 9) + (lnA << 4) + (reg << 2);
            off ^= (off >> 2) & 0x60;
            *(uint32_t*)(smem + OFF_AHI + off) = *(uint32_t*)&hp;
        }
        float sl, sh, s2l, s2h;
        upk2(accS, sl, sh);
        upk2(accS2, s2l, s2h);
        smf[OFF_STS  / 4 + m * 2 + half] = sl + sh;
        smf[OFF_STS2 / 4 + m * 2 + half] = s2l + s2h;
    }
    __syncthreads();

    // ---- GEMM + fused epilogue: two N-halves of 128 cols ----
    const int wm = w & 1, wn = w >> 1;
    const int g = lane >> 2, cq = lane & 3;
    const uint32_t laneOff = ((uint32_t)lane << 4) ^ (((uint32_t)lane & 0x18) << 2);
    float part[8] = {0.f, 0.f, 0.f, 0.f, 0.f, 0.f, 0.f, 0.f};

#pragma unroll
    for (int nh = 0; nh < 2; nh++) {
        float acc[4][4][4];
#pragma unroll
        for (int mt = 0; mt < 4; mt++)
#pragma unroll
            for (int nt = 0; nt < 4; nt++)
#pragma unroll
                for (int e = 0; e < 4; e++) acc[mt][nt][e] = 0.f;

        // B fragments straight from global (L2-resident), uint4 units
        const uint4* gBp = (const uint4*)g_Bpk;
        const int pbase = nh * 8 + wn * 2;
        uint4 bh[2][2];
        bh[0][0] = __ldg(gBp + 0 * 512 + (pbase + 0) * 32 + lane);
        bh[0][1] = __ldg(gBp + 0 * 512 + (pbase + 1) * 32 + lane);
        bh[1][0] = __ldg(gBp + 1 * 512 + (pbase + 0) * 32 + lane);
        bh[1][1] = __ldg(gBp + 1 * 512 + (pbase + 1) * 32 + lane);

#pragma unroll 4
        for (int ks = 0; ks < 16; ks++) {
            uint32_t ah[4][4];
#pragma unroll
            for (int mt = 0; mt < 4; mt++) {
                const uint32_t aRow = (((uint32_t)((wm * 4 + mt) * 16 + ks)) << 9) + laneOff;
                LDS128(ah[mt], sbase + OFF_AHI + aRow);
            }
            const uint4 b0 = bh[ks & 1][0];
            const uint4 b1 = bh[ks & 1][1];
            if (ks + 2 < 16) {
                bh[ks & 1][0] = __ldg(gBp + (ks + 2) * 512 + (pbase + 0) * 32 + lane);
                bh[ks & 1][1] = __ldg(gBp + (ks + 2) * 512 + (pbase + 1) * 32 + lane);
            }
#pragma unroll
            for (int mt = 0; mt < 4; mt++) {
                MMA_F32(acc[mt][0], ah[mt], b0.x, b0.y);
                MMA_F32(acc[mt][1], ah[mt], b0.z, b0.w);
                MMA_F32(acc[mt][2], ah[mt], b1.x, b1.y);
                MMA_F32(acc[mt][3], ah[mt], b1.z, b1.w);
            }
        }

        // fused epilogue for this half: LN fold + exact GELU + W2 dot
        float rstd[8], mr[8];
#pragma unroll
        for (int idx = 0; idx < 8; idx++) {
            const int row = wm * 64 + (idx >> 1) * 16 + (idx & 1) * 8 + g;
            const float ssum = smf[OFF_STS / 4 + row * 2] + smf[OFF_STS / 4 + row * 2 + 1];
            const float q2   = smf[OFF_STS2 / 4 + row * 2] + smf[OFF_STS2 / 4 + row * 2 + 1];
            const float mu   = ssum * (1.0f / HIDDEN);
            const float var  = q2 * (1.0f / HIDDEN) - mu * mu;
            rstd[idx] = rsqrtf(var + EPS_LN);
            mr[idx]   = mu * rstd[idx];
        }
#pragma unroll
        for (int mt = 0; mt < 4; mt++)
#pragma unroll
            for (int nt = 0; nt < 4; nt++) {
                const int j = nh * 128 + wn * 32 + nt * 8 + cq * 2;
                const float cs0 = smf[OFF_CS / 4 + j],  cs1 = smf[OFF_CS / 4 + j + 1];
                const float gs0 = smf[OFF_GS / 4 + j],  gs1 = smf[OFF_GS / 4 + j + 1];
                const float w20 = smf[OFF_W2S / 4 + j], w21 = smf[OFF_W2S / 4 + j + 1];
#pragma unroll
                for (int q = 0; q < 2; q++) {
                    const int idx = mt * 2 + q;
                    const float o0 = fmaf(rstd[idx], acc[mt][nt][q * 2 + 0],
                                          fmaf(-mr[idx], gs0, cs0));
                    const float o1 = fmaf(rstd[idx], acc[mt][nt][q * 2 + 1],
                                          fmaf(-mr[idx], gs1, cs1));
                    part[idx] = fmaf(gelu_exact(o0), w20, part[idx]);
                    part[idx] = fmaf(gelu_exact(o1), w21, part[idx]);
                }
            }
    }

#pragma unroll
    for (int idx = 0; idx < 8; idx++) {
        const int row = wm * 64 + (idx >> 1) * 16 + (idx & 1) * 8 + g;
        smf[OFF_RED / 4 + row * 16 + wn * 4 + cq] = part[idx];
    }
    __syncthreads();

    if (tid < GRP * T_HOR) {
        const int lno = tid / T_HOR, to = tid % T_HOR;
        const float4* rr = (const float4*)&smf[OFF_RED / 4 + tid * 16];
        float4 r0 = rr[0], r1 = rr[1], r2 = rr[2], r3 = rr[3];
        float s = ((r0.x + r0.y) + (r0.z + r0.w)) + ((r1.x + r1.y) + (r1.z + r1.w)) +
                  ((r2.x + r2.y) + (r2.z + r2.w)) + ((r3.x + r3.y) + (r3.z + r3.w));
        out[(size_t)(b * T_HOR + to) * N_SZ + (n0 + lno)] = s + b2[0];
    }
}

extern "C" void kernel_launch(void* const* d_in, const int* in_sizes, int n_in,
                              void* d_out, int out_size) {
    const float* final_h    = (const float*)d_in[0];
    const float* future_met = (const float*)d_in[1];
    const float* step_q     = (const float*)d_in[2];
    const float* W_fm       = (const float*)d_in[3];
    const float* b_fm       = (const float*)d_in[4];
    const float* gamma      = (const float*)d_in[5];
    const float* beta       = (const float*)d_in[6];
    const float* W1         = (const float*)d_in[7];
    const float* b1         = (const float*)d_in[8];
    const float* W2         = (const float*)d_in[9];
    const float* b2         = (const float*)d_in[10];
    float* out = (float*)d_out;

    prep_w1<<<128, 256>>>(W1);
    prep_cg<<<1, 256>>>(W1, gamma, beta, b1, W2);

    cudaFuncSetAttribute(dhh_main, cudaFuncAttributeMaxDynamicSharedMemorySize, SMEM_TOTAL);
    dhh_main<<<NCTA, TPB, SMEM_TOTAL>>>(final_h, future_met, step_q, W_fm, b_fm,
                                        gamma, b2, out);
}